// round 13
// baseline (speedup 1.0000x reference)
#include <cuda_runtime.h>
#include <cstdint>
#include <cstddef>

#define Hc 192
#define Wc 192
#define HWc (Hc*Wc)            // 36864
#define Bc 4
#define NPIX (Bc*HWc)          // 147456
#define CINc 64
#define CBc 16
#define CMc 256
#define KTOP 16

#define SZ_TI  (Bc*3*HWc)              // 442368
#define OFF_MSP (SZ_TI)
#define SZ_MSP (Bc*CMc*HWc)            // 37748736
#define OFF_PAL (SZ_TI + SZ_MSP)       // 38191104

// ---------------- scratch (__device__ globals; no allocations) ----------------
__device__ float         g_x[(size_t)NPIX * CBc];        // bottleneck pre-BN, [pix][16]
__device__ float         g_sum[CBc];
__device__ float         g_sumsq[CBc];
__device__ float         g_scale[CBc];
__device__ float         g_shift[CBc];
__device__ float         g_tk_sm[(size_t)NPIX * KTOP];   // softmax values
__device__ unsigned char g_tk_idx[(size_t)NPIX * KTOP];  // color indices
__device__ float         g_den[Bc * CMc];
__device__ float         g_num[Bc * 3 * CMc];

// ---------------- K0: zero accumulators ----------------
__global__ void k_zero() {
    int t = blockIdx.x * 256 + threadIdx.x;
    if (t < CBc)          { g_sum[t] = 0.f; g_sumsq[t] = 0.f; }
    if (t < Bc * CMc)     g_den[t] = 0.f;
    if (t < Bc * 3 * CMc) g_num[t] = 0.f;
}

// ---------------- K1: 1x1 conv 64->16 + channel stats ----------------
__global__ __launch_bounds__(256) void k_bneck(const float* __restrict__ bf,
                                               const float* __restrict__ w,
                                               const float* __restrict__ bias) {
    __shared__ float s_wt[CINc * CBc];   // transposed: [ch][o]
    __shared__ float s_sum[CBc], s_sq[CBc];
    int tid = threadIdx.x;
    for (int i = tid; i < CINc * CBc; i += 256) {
        int ch = i >> 4, o = i & 15;
        s_wt[i] = w[o * CINc + ch];
    }
    if (tid < CBc) { s_sum[tid] = 0.f; s_sq[tid] = 0.f; }
    __syncthreads();

    int p  = blockIdx.x * 256 + tid;
    int b  = p / HWc;
    int pp = p - b * HWc;
    const float* src = bf + (size_t)b * CINc * HWc + pp;

    float acc[16];
#pragma unroll
    for (int o = 0; o < 16; ++o) acc[o] = __ldg(&bias[o]);

#pragma unroll 4
    for (int ch = 0; ch < CINc; ++ch) {
        float v = src[(size_t)ch * HWc];
        const float4* w4 = (const float4*)(s_wt + ch * 16);
        float4 q0 = w4[0], q1 = w4[1], q2 = w4[2], q3 = w4[3];
        acc[0]  = fmaf(v, q0.x, acc[0]);  acc[1]  = fmaf(v, q0.y, acc[1]);
        acc[2]  = fmaf(v, q0.z, acc[2]);  acc[3]  = fmaf(v, q0.w, acc[3]);
        acc[4]  = fmaf(v, q1.x, acc[4]);  acc[5]  = fmaf(v, q1.y, acc[5]);
        acc[6]  = fmaf(v, q1.z, acc[6]);  acc[7]  = fmaf(v, q1.w, acc[7]);
        acc[8]  = fmaf(v, q2.x, acc[8]);  acc[9]  = fmaf(v, q2.y, acc[9]);
        acc[10] = fmaf(v, q2.z, acc[10]); acc[11] = fmaf(v, q2.w, acc[11]);
        acc[12] = fmaf(v, q3.x, acc[12]); acc[13] = fmaf(v, q3.y, acc[13]);
        acc[14] = fmaf(v, q3.z, acc[14]); acc[15] = fmaf(v, q3.w, acc[15]);
    }

    float4* dst = (float4*)(g_x + (size_t)p * 16);
    dst[0] = make_float4(acc[0],  acc[1],  acc[2],  acc[3]);
    dst[1] = make_float4(acc[4],  acc[5],  acc[6],  acc[7]);
    dst[2] = make_float4(acc[8],  acc[9],  acc[10], acc[11]);
    dst[3] = make_float4(acc[12], acc[13], acc[14], acc[15]);

    int lane = tid & 31;
#pragma unroll
    for (int o = 0; o < 16; ++o) {
        float sv = acc[o];
        float qv = acc[o] * acc[o];
#pragma unroll
        for (int off = 16; off > 0; off >>= 1) {
            sv += __shfl_xor_sync(0xffffffffu, sv, off);
            qv += __shfl_xor_sync(0xffffffffu, qv, off);
        }
        if (lane == 0) { atomicAdd(&s_sum[o], sv); atomicAdd(&s_sq[o], qv); }
    }
    __syncthreads();
    if (tid < CBc) {
        atomicAdd(&g_sum[tid],   s_sum[tid]);
        atomicAdd(&g_sumsq[tid], s_sq[tid]);
    }
}

// ---------------- K2: finalize BN scale/shift ----------------
__global__ void k_bnfin(const float* __restrict__ gamma, const float* __restrict__ beta) {
    int i = threadIdx.x;
    if (i < CBc) {
        float inv  = 1.0f / (float)NPIX;
        float mean = g_sum[i] * inv;
        float var  = g_sumsq[i] * inv - mean * mean;
        float r    = rsqrtf(var + 1e-5f);
        float sc   = gamma[i] * r;
        g_scale[i] = sc;
        g_shift[i] = beta[i] - mean * sc;
    }
}

// flip-float: order-preserving map float->uint32 (full precision)
__device__ __forceinline__ unsigned flip_f(float f) {
    unsigned u = __float_as_uint(f);
    return (u & 0x80000000u) ? ~u : (u | 0x80000000u);
}
__device__ __forceinline__ float unflip_f(unsigned u) {
    return (u & 0x80000000u) ? __uint_as_float(u & 0x7FFFFFFFu)
                             : __uint_as_float(~u);
}

// ---------------- K3: mask GEMM + top-16 + softmax + scatter ----------------
// warp-per-pixel; lane owns 8 colors: {4l..4l+3, 128+4l..128+4l+3}
// 64-bit keys: [63:32]=flipped full-precision logit, [31:0]=(255-color) tie-break
__global__ __launch_bounds__(256) void k_mask(const float* __restrict__ w_mask,
                                              float* __restrict__ out) {
    __shared__ float ws_t[CBc * CMc];     // transposed: [i][c], 16KB
    __shared__ float s_feat[8][16];
    __shared__ float s_scale[16], s_shift[16];
    int tid = threadIdx.x;
    for (int i = tid; i < CBc * CMc; i += 256) {
        int r = i >> 8, c = i & 255;
        ws_t[i] = w_mask[c * CBc + r];
    }
    if (tid < 16) { s_scale[tid] = g_scale[tid]; s_shift[tid] = g_shift[tid]; }
    __syncthreads();

    int warp = tid >> 5, lane = tid & 31;
    int p0 = blockIdx.x * 128 + warp * 16;
    int b  = p0 / HWc;   // blocks never straddle batches (36864 % 128 == 0)

#pragma unroll 1
    for (int it = 0; it < 16; ++it) {
        int p  = p0 + it;
        int pp = p - b * HWc;

        __syncwarp();
        if (lane < 16) {
            float xv = g_x[(size_t)p * 16 + lane];
            s_feat[warp][lane] = fmaxf(fmaf(xv, s_scale[lane], s_shift[lane]), 0.f);
        }
        __syncwarp();

        // logits: 8 colors per lane
        float a[8] = {0.f,0.f,0.f,0.f,0.f,0.f,0.f,0.f};
#pragma unroll
        for (int i = 0; i < 16; ++i) {
            float f = s_feat[warp][i];
            const float4* row4 = (const float4*)(ws_t + i * CMc);
            float4 w0 = row4[lane];
            float4 w1 = row4[lane + 32];
            a[0] = fmaf(f, w0.x, a[0]); a[1] = fmaf(f, w0.y, a[1]);
            a[2] = fmaf(f, w0.z, a[2]); a[3] = fmaf(f, w0.w, a[3]);
            a[4] = fmaf(f, w1.x, a[4]); a[5] = fmaf(f, w1.y, a[5]);
            a[6] = fmaf(f, w1.z, a[6]); a[7] = fmaf(f, w1.w, a[7]);
        }

        // pack 64-bit keys (full logit precision; smaller index wins ties)
        unsigned long long k[8];
#pragma unroll
        for (int m = 0; m < 8; ++m) {
            int c = (m < 4) ? (4 * lane + m) : (128 + 4 * lane + (m - 4));
            k[m] = ((unsigned long long)flip_f(a[m]) << 32)
                 | (unsigned long long)(255 - c);
        }

        // Batcher odd-even sort-8, descending (19 CAS)
#define CAS(i, j) { unsigned long long x_ = k[i], y_ = k[j]; \
                    k[i] = x_ > y_ ? x_ : y_; k[j] = x_ > y_ ? y_ : x_; }
        CAS(0,1) CAS(2,3) CAS(4,5) CAS(6,7)
        CAS(0,2) CAS(1,3) CAS(4,6) CAS(5,7)
        CAS(1,2) CAS(5,6)
        CAS(0,4) CAS(1,5) CAS(2,6) CAS(3,7)
        CAS(2,4) CAS(3,5)
        CAS(1,2) CAS(3,4) CAS(5,6)
#undef CAS

        unsigned long long m0key = 0ull, mykey = 0ull;
#pragma unroll
        for (int r = 0; r < 16; ++r) {
            unsigned long long lv = k[0];
#pragma unroll
            for (int off = 16; off > 0; off >>= 1) {
                unsigned long long o_ = __shfl_xor_sync(0xffffffffu, lv, off);
                lv = o_ > lv ? o_ : lv;
            }
            if (r == 0)    m0key = lv;
            if (lane == r) mykey = lv;
            bool win = (k[0] == lv);
#pragma unroll
            for (int t = 0; t < 7; ++t) k[t] = win ? k[t + 1] : k[t];
            k[7] = win ? 0ull : k[7];
        }

        float e = 0.f;
        int col = 0;
        if (lane < 16) {
            col = 255 - (int)(mykey & 0xFFFFFFFFull);
            float v  = unflip_f((unsigned)(mykey >> 32));
            float v0 = unflip_f((unsigned)(m0key >> 32));
            e = __expf(v - v0);
        }
        float ssum = e;
#pragma unroll
        for (int off = 16; off > 0; off >>= 1)
            ssum += __shfl_xor_sync(0xffffffffu, ssum, off);

        if (lane < 16) {
            float sm = e / ssum;
            out[(size_t)OFF_MSP + (size_t)(b * CMc + col) * HWc + pp] = sm;
            g_tk_sm[(size_t)p * KTOP + lane]  = sm;
            g_tk_idx[(size_t)p * KTOP + lane] = (unsigned char)col;
        }
    }
}

// ---------------- K4: palette num/den via dense coalesced reduction ----------------
// grid = 1024: [b(2b)][kgroup(5b)][slice(3b)]; 8 colors per block
__global__ __launch_bounds__(256) void k_pal_acc(const float* __restrict__ img,
                                                 const float* __restrict__ out) {
    int s  = blockIdx.x & 7;
    int kg = (blockIdx.x >> 3) & 31;
    int b  = blockIdx.x >> 8;
    int k0 = kg * 8;
    const float* msp = out + (size_t)OFF_MSP + (size_t)(b * CMc + k0) * HWc;
    const float* im0 = img + (size_t)(b * 3) * HWc;

    float d[8]  = {0,0,0,0,0,0,0,0};
    float rr[8] = {0,0,0,0,0,0,0,0};
    float gg[8] = {0,0,0,0,0,0,0,0};
    float bb[8] = {0,0,0,0,0,0,0,0};

    const int SLICE = HWc / 8;
    for (int i = s * SLICE + threadIdx.x; i < (s + 1) * SLICE; i += 256) {
        float ir = im0[i];
        float ig = im0[HWc + i];
        float ib = im0[2 * HWc + i];
#pragma unroll
        for (int kk = 0; kk < 8; ++kk) {
            float v = msp[(size_t)kk * HWc + i];
            if (v != 0.f) {
                d[kk]  += v;
                rr[kk] = fmaf(v, ir, rr[kk]);
                gg[kk] = fmaf(v, ig, gg[kk]);
                bb[kk] = fmaf(v, ib, bb[kk]);
            }
        }
    }

    int lane = threadIdx.x & 31;
#pragma unroll
    for (int kk = 0; kk < 8; ++kk) {
        float vd = d[kk], vr = rr[kk], vg = gg[kk], vb = bb[kk];
#pragma unroll
        for (int off = 16; off > 0; off >>= 1) {
            vd += __shfl_xor_sync(0xffffffffu, vd, off);
            vr += __shfl_xor_sync(0xffffffffu, vr, off);
            vg += __shfl_xor_sync(0xffffffffu, vg, off);
            vb += __shfl_xor_sync(0xffffffffu, vb, off);
        }
        if (lane == 0) {
            atomicAdd(&g_den[b * CMc + k0 + kk], vd);
            atomicAdd(&g_num[(b * 3 + 0) * CMc + k0 + kk], vr);
            atomicAdd(&g_num[(b * 3 + 1) * CMc + k0 + kk], vg);
            atomicAdd(&g_num[(b * 3 + 2) * CMc + k0 + kk], vb);
        }
    }
}

// ---------------- K4b: palette = num/(den+1e-8) ----------------
__global__ void k_pal_fin(float* __restrict__ out) {
    int t = blockIdx.x * 256 + threadIdx.x;
    if (t < Bc * 3 * CMc) {
        int b = t / (3 * CMc);
        int k = t & (CMc - 1);
        float den = g_den[b * CMc + k] + 1e-8f;
        out[(size_t)OFF_PAL + t] = g_num[t] / den;
    }
}

// ---------------- K5: transformed image ----------------
__global__ __launch_bounds__(256) void k_transform(float* __restrict__ out) {
    int p  = blockIdx.x * 256 + threadIdx.x;
    int b  = p / HWc;
    int pp = p - b * HWc;

    const float4* sm4 = (const float4*)(g_tk_sm + (size_t)p * KTOP);
    const uint4*  id4 = (const uint4*)(g_tk_idx + (size_t)p * KTOP);
    uint4 iu = *id4;
    unsigned words[4] = {iu.x, iu.y, iu.z, iu.w};
    const float* pal = out + (size_t)OFF_PAL + (size_t)b * 3 * CMc;

    float ax = 0.f, ay = 0.f, az = 0.f;
#pragma unroll
    for (int q = 0; q < 4; ++q) {
        float4 sv = sm4[q];
        float svv[4] = {sv.x, sv.y, sv.z, sv.w};
#pragma unroll
        for (int t = 0; t < 4; ++t) {
            int   idx = (int)((words[q] >> (8 * t)) & 255u);
            float smv = svv[t];
            ax = fmaf(smv, pal[idx],             ax);
            ay = fmaf(smv, pal[CMc + idx],       ay);
            az = fmaf(smv, pal[2 * CMc + idx],   az);
        }
    }
    out[(size_t)(b * 3 + 0) * HWc + pp] = ax;
    out[(size_t)(b * 3 + 1) * HWc + pp] = ay;
    out[(size_t)(b * 3 + 2) * HWc + pp] = az;
}

// ---------------- launch ----------------
extern "C" void kernel_launch(void* const* d_in, const int* in_sizes, int n_in,
                              void* d_out, int out_size) {
    const float* img       = (const float*)d_in[0];
    const float* base_feat = (const float*)d_in[1];
    const float* w_bneck   = (const float*)d_in[2];
    const float* b_bneck   = (const float*)d_in[3];
    const float* bn_gamma  = (const float*)d_in[4];
    const float* bn_beta   = (const float*)d_in[5];
    const float* w_mask    = (const float*)d_in[6];
    float* out = (float*)d_out;

    k_zero<<<12, 256>>>();
    cudaMemsetAsync(out + OFF_MSP, 0, (size_t)SZ_MSP * sizeof(float), 0);
    k_bneck<<<NPIX / 256, 256>>>(base_feat, w_bneck, b_bneck);
    k_bnfin<<<1, 32>>>(bn_gamma, bn_beta);
    k_mask<<<NPIX / 128, 256>>>(w_mask, out);
    k_pal_acc<<<1024, 256>>>(img, out);
    k_pal_fin<<<12, 256>>>(out);
    k_transform<<<NPIX / 256, 256>>>(out);
}

// round 16
// speedup vs baseline: 1.3718x; 1.3718x over previous
#include <cuda_runtime.h>
#include <cstdint>
#include <cstddef>

#define Hc 192
#define Wc 192
#define HWc (Hc*Wc)            // 36864
#define Bc 4
#define NPIX (Bc*HWc)          // 147456
#define CINc 64
#define CBc 16
#define CMc 256
#define KTOP 16

#define SZ_TI  (Bc*3*HWc)              // 442368
#define OFF_MSP (SZ_TI)
#define SZ_MSP (Bc*CMc*HWc)            // 37748736
#define OFF_PAL (SZ_TI + SZ_MSP)       // 38191104

// ---------------- scratch (__device__ globals; no allocations) ----------------
__device__ float         g_x[(size_t)NPIX * CBc];        // bottleneck pre-BN, [pix][16]
__device__ float         g_sum[CBc];
__device__ float         g_sumsq[CBc];
__device__ float         g_scale[CBc];
__device__ float         g_shift[CBc];
__device__ float         g_tk_sm[(size_t)NPIX * KTOP];   // softmax values
__device__ unsigned char g_tk_idx[(size_t)NPIX * KTOP];  // color indices
__device__ float         g_den[Bc * CMc];
__device__ float         g_num[Bc * 3 * CMc];

// ---------------- K0: zero accumulators ----------------
__global__ void k_zero() {
    int t = blockIdx.x * 256 + threadIdx.x;
    if (t < CBc)          { g_sum[t] = 0.f; g_sumsq[t] = 0.f; }
    if (t < Bc * CMc)     g_den[t] = 0.f;
    if (t < Bc * 3 * CMc) g_num[t] = 0.f;
}

// ---------------- K1: 1x1 conv 64->16 + channel stats ----------------
__global__ __launch_bounds__(256) void k_bneck(const float* __restrict__ bf,
                                               const float* __restrict__ w,
                                               const float* __restrict__ bias) {
    __shared__ float s_wt[CINc * CBc];   // transposed: [ch][o]
    __shared__ float s_sum[CBc], s_sq[CBc];
    int tid = threadIdx.x;
    for (int i = tid; i < CINc * CBc; i += 256) {
        int ch = i >> 4, o = i & 15;
        s_wt[i] = w[o * CINc + ch];
    }
    if (tid < CBc) { s_sum[tid] = 0.f; s_sq[tid] = 0.f; }
    __syncthreads();

    int p  = blockIdx.x * 256 + tid;
    int b  = p / HWc;
    int pp = p - b * HWc;
    const float* src = bf + (size_t)b * CINc * HWc + pp;

    float acc[16];
#pragma unroll
    for (int o = 0; o < 16; ++o) acc[o] = __ldg(&bias[o]);

#pragma unroll 4
    for (int ch = 0; ch < CINc; ++ch) {
        float v = src[(size_t)ch * HWc];
        const float4* w4 = (const float4*)(s_wt + ch * 16);
        float4 q0 = w4[0], q1 = w4[1], q2 = w4[2], q3 = w4[3];
        acc[0]  = fmaf(v, q0.x, acc[0]);  acc[1]  = fmaf(v, q0.y, acc[1]);
        acc[2]  = fmaf(v, q0.z, acc[2]);  acc[3]  = fmaf(v, q0.w, acc[3]);
        acc[4]  = fmaf(v, q1.x, acc[4]);  acc[5]  = fmaf(v, q1.y, acc[5]);
        acc[6]  = fmaf(v, q1.z, acc[6]);  acc[7]  = fmaf(v, q1.w, acc[7]);
        acc[8]  = fmaf(v, q2.x, acc[8]);  acc[9]  = fmaf(v, q2.y, acc[9]);
        acc[10] = fmaf(v, q2.z, acc[10]); acc[11] = fmaf(v, q2.w, acc[11]);
        acc[12] = fmaf(v, q3.x, acc[12]); acc[13] = fmaf(v, q3.y, acc[13]);
        acc[14] = fmaf(v, q3.z, acc[14]); acc[15] = fmaf(v, q3.w, acc[15]);
    }

    float4* dst = (float4*)(g_x + (size_t)p * 16);
    dst[0] = make_float4(acc[0],  acc[1],  acc[2],  acc[3]);
    dst[1] = make_float4(acc[4],  acc[5],  acc[6],  acc[7]);
    dst[2] = make_float4(acc[8],  acc[9],  acc[10], acc[11]);
    dst[3] = make_float4(acc[12], acc[13], acc[14], acc[15]);

    int lane = tid & 31;
#pragma unroll
    for (int o = 0; o < 16; ++o) {
        float sv = acc[o];
        float qv = acc[o] * acc[o];
#pragma unroll
        for (int off = 16; off > 0; off >>= 1) {
            sv += __shfl_xor_sync(0xffffffffu, sv, off);
            qv += __shfl_xor_sync(0xffffffffu, qv, off);
        }
        if (lane == 0) { atomicAdd(&s_sum[o], sv); atomicAdd(&s_sq[o], qv); }
    }
    __syncthreads();
    if (tid < CBc) {
        atomicAdd(&g_sum[tid],   s_sum[tid]);
        atomicAdd(&g_sumsq[tid], s_sq[tid]);
    }
}

// ---------------- K2: finalize BN scale/shift ----------------
__global__ void k_bnfin(const float* __restrict__ gamma, const float* __restrict__ beta) {
    int i = threadIdx.x;
    if (i < CBc) {
        float inv  = 1.0f / (float)NPIX;
        float mean = g_sum[i] * inv;
        float var  = g_sumsq[i] * inv - mean * mean;
        float r    = rsqrtf(var + 1e-5f);
        float sc   = gamma[i] * r;
        g_scale[i] = sc;
        g_shift[i] = beta[i] - mean * sc;
    }
}

// flip-float: order-preserving map float->uint32 (full precision)
__device__ __forceinline__ unsigned flip_f(float f) {
    unsigned u = __float_as_uint(f);
    return (u & 0x80000000u) ? ~u : (u | 0x80000000u);
}
__device__ __forceinline__ float unflip_f(unsigned u) {
    return (u & 0x80000000u) ? __uint_as_float(u & 0x7FFFFFFFu)
                             : __uint_as_float(~u);
}

// ---------------- K3: mask GEMM + top-16 + softmax + scatter ----------------
// warp-per-pixel; lane owns 8 colors: {4l..4l+3, 128+4l..128+4l+3}
// 32-bit full-precision keys + color payload. Per round:
//   lv = warp max (REDUX.MAX); wcol = min color among tied heads (REDUX.MIN).
// Stable in-lane sort keeps equal values in ascending-color order, and lanes
// own disjoint colors, so this reproduces jax.lax.top_k's tie semantics
// (value desc, index asc) exactly. Exactly one lane pops per round.
__global__ __launch_bounds__(256) void k_mask(const float* __restrict__ w_mask,
                                              float* __restrict__ out) {
    __shared__ float ws_t[CBc * CMc];     // transposed: [i][c], 16KB
    __shared__ float s_feat[8][16];
    __shared__ float s_scale[16], s_shift[16];
    int tid = threadIdx.x;
    for (int i = tid; i < CBc * CMc; i += 256) {
        int r = i >> 8, c = i & 255;
        ws_t[i] = w_mask[c * CBc + r];
    }
    if (tid < 16) { s_scale[tid] = g_scale[tid]; s_shift[tid] = g_shift[tid]; }
    __syncthreads();

    int warp = tid >> 5, lane = tid & 31;
    int p0 = blockIdx.x * 128 + warp * 16;
    int b  = p0 / HWc;   // blocks never straddle batches (36864 % 128 == 0)

#pragma unroll 1
    for (int it = 0; it < 16; ++it) {
        int p  = p0 + it;
        int pp = p - b * HWc;

        __syncwarp();
        if (lane < 16) {
            float xv = g_x[(size_t)p * 16 + lane];
            s_feat[warp][lane] = fmaxf(fmaf(xv, s_scale[lane], s_shift[lane]), 0.f);
        }
        __syncwarp();

        // logits: 8 colors per lane
        float a[8] = {0.f,0.f,0.f,0.f,0.f,0.f,0.f,0.f};
#pragma unroll
        for (int i = 0; i < 16; ++i) {
            float f = s_feat[warp][i];
            const float4* row4 = (const float4*)(ws_t + i * CMc);
            float4 w0 = row4[lane];
            float4 w1 = row4[lane + 32];
            a[0] = fmaf(f, w0.x, a[0]); a[1] = fmaf(f, w0.y, a[1]);
            a[2] = fmaf(f, w0.z, a[2]); a[3] = fmaf(f, w0.w, a[3]);
            a[4] = fmaf(f, w1.x, a[4]); a[5] = fmaf(f, w1.y, a[5]);
            a[6] = fmaf(f, w1.z, a[6]); a[7] = fmaf(f, w1.w, a[7]);
        }

        // 32-bit keys (full precision) + color payload (ascending within lane)
        unsigned v[8]; int c[8];
#pragma unroll
        for (int m = 0; m < 8; ++m) {
            c[m] = (m < 4) ? (4 * lane + m) : (128 + 4 * lane + (m - 4));
            v[m] = flip_f(a[m]);
        }

        // Batcher odd-even sort-8, descending, STABLE (swap on strict <):
        // equal values remain in ascending-color order within the lane.
#define CAS(i, j) { bool sw_ = v[i] < v[j]; \
                    unsigned tv_ = v[i]; v[i] = sw_ ? v[j] : v[i]; v[j] = sw_ ? tv_ : v[j]; \
                    int tc_ = c[i]; c[i] = sw_ ? c[j] : c[i]; c[j] = sw_ ? tc_ : c[j]; }
        CAS(0,1) CAS(2,3) CAS(4,5) CAS(6,7)
        CAS(0,2) CAS(1,3) CAS(4,6) CAS(5,7)
        CAS(1,2) CAS(5,6)
        CAS(0,4) CAS(1,5) CAS(2,6) CAS(3,7)
        CAS(2,4) CAS(3,5)
        CAS(1,2) CAS(3,4) CAS(5,6)
#undef CAS

        unsigned v0max = 0u, myv = 0u;
        int myc = 0;
#pragma unroll
        for (int r = 0; r < 16; ++r) {
            unsigned lv = __reduce_max_sync(0xffffffffu, v[0]);
            bool tied   = (v[0] == lv);
            unsigned cand = tied ? (unsigned)c[0] : 0x40000000u;
            unsigned wcol = __reduce_min_sync(0xffffffffu, cand);   // warp-uniform
            if (r == 0)    v0max = lv;
            if (lane == r) { myv = lv; myc = (int)wcol; }
            bool win = tied && ((unsigned)c[0] == wcol);             // exactly one lane
#pragma unroll
            for (int t = 0; t < 7; ++t) {
                v[t] = win ? v[t + 1] : v[t];
                c[t] = win ? c[t + 1] : c[t];
            }
            v[7] = win ? 0u : v[7];
        }

        float e = 0.f;
        if (lane < 16) {
            float val = unflip_f(myv);
            float v0  = unflip_f(v0max);
            e = __expf(val - v0);
        }
        float ssum = e;
#pragma unroll
        for (int off = 16; off > 0; off >>= 1)
            ssum += __shfl_xor_sync(0xffffffffu, ssum, off);

        if (lane < 16) {
            float sm = e / ssum;
            out[(size_t)OFF_MSP + (size_t)(b * CMc + myc) * HWc + pp] = sm;
            g_tk_sm[(size_t)p * KTOP + lane]  = sm;
            g_tk_idx[(size_t)p * KTOP + lane] = (unsigned char)myc;
        }
    }
}

// ---------------- K4: palette num/den via dense coalesced reduction ----------------
// grid = 1024: [b(2b)][kgroup(5b)][slice(3b)]; 8 colors per block
__global__ __launch_bounds__(256) void k_pal_acc(const float* __restrict__ img,
                                                 const float* __restrict__ out) {
    int s  = blockIdx.x & 7;
    int kg = (blockIdx.x >> 3) & 31;
    int b  = blockIdx.x >> 8;
    int k0 = kg * 8;
    const float* msp = out + (size_t)OFF_MSP + (size_t)(b * CMc + k0) * HWc;
    const float* im0 = img + (size_t)(b * 3) * HWc;

    float d[8]  = {0,0,0,0,0,0,0,0};
    float rr[8] = {0,0,0,0,0,0,0,0};
    float gg[8] = {0,0,0,0,0,0,0,0};
    float bb[8] = {0,0,0,0,0,0,0,0};

    const int SLICE = HWc / 8;
    for (int i = s * SLICE + threadIdx.x; i < (s + 1) * SLICE; i += 256) {
        float ir = im0[i];
        float ig = im0[HWc + i];
        float ib = im0[2 * HWc + i];
#pragma unroll
        for (int kk = 0; kk < 8; ++kk) {
            float v = msp[(size_t)kk * HWc + i];
            if (v != 0.f) {
                d[kk]  += v;
                rr[kk] = fmaf(v, ir, rr[kk]);
                gg[kk] = fmaf(v, ig, gg[kk]);
                bb[kk] = fmaf(v, ib, bb[kk]);
            }
        }
    }

    int lane = threadIdx.x & 31;
#pragma unroll
    for (int kk = 0; kk < 8; ++kk) {
        float vd = d[kk], vr = rr[kk], vg = gg[kk], vb = bb[kk];
#pragma unroll
        for (int off = 16; off > 0; off >>= 1) {
            vd += __shfl_xor_sync(0xffffffffu, vd, off);
            vr += __shfl_xor_sync(0xffffffffu, vr, off);
            vg += __shfl_xor_sync(0xffffffffu, vg, off);
            vb += __shfl_xor_sync(0xffffffffu, vb, off);
        }
        if (lane == 0) {
            atomicAdd(&g_den[b * CMc + k0 + kk], vd);
            atomicAdd(&g_num[(b * 3 + 0) * CMc + k0 + kk], vr);
            atomicAdd(&g_num[(b * 3 + 1) * CMc + k0 + kk], vg);
            atomicAdd(&g_num[(b * 3 + 2) * CMc + k0 + kk], vb);
        }
    }
}

// ---------------- K4b: palette = num/(den+1e-8) ----------------
__global__ void k_pal_fin(float* __restrict__ out) {
    int t = blockIdx.x * 256 + threadIdx.x;
    if (t < Bc * 3 * CMc) {
        int b = t / (3 * CMc);
        int k = t & (CMc - 1);
        float den = g_den[b * CMc + k] + 1e-8f;
        out[(size_t)OFF_PAL + t] = g_num[t] / den;
    }
}

// ---------------- K5: transformed image ----------------
__global__ __launch_bounds__(256) void k_transform(float* __restrict__ out) {
    int p  = blockIdx.x * 256 + threadIdx.x;
    int b  = p / HWc;
    int pp = p - b * HWc;

    const float4* sm4 = (const float4*)(g_tk_sm + (size_t)p * KTOP);
    const uint4*  id4 = (const uint4*)(g_tk_idx + (size_t)p * KTOP);
    uint4 iu = *id4;
    unsigned words[4] = {iu.x, iu.y, iu.z, iu.w};
    const float* pal = out + (size_t)OFF_PAL + (size_t)b * 3 * CMc;

    float ax = 0.f, ay = 0.f, az = 0.f;
#pragma unroll
    for (int q = 0; q < 4; ++q) {
        float4 sv = sm4[q];
        float svv[4] = {sv.x, sv.y, sv.z, sv.w};
#pragma unroll
        for (int t = 0; t < 4; ++t) {
            int   idx = (int)((words[q] >> (8 * t)) & 255u);
            float smv = svv[t];
            ax = fmaf(smv, pal[idx],             ax);
            ay = fmaf(smv, pal[CMc + idx],       ay);
            az = fmaf(smv, pal[2 * CMc + idx],   az);
        }
    }
    out[(size_t)(b * 3 + 0) * HWc + pp] = ax;
    out[(size_t)(b * 3 + 1) * HWc + pp] = ay;
    out[(size_t)(b * 3 + 2) * HWc + pp] = az;
}

// ---------------- launch ----------------
extern "C" void kernel_launch(void* const* d_in, const int* in_sizes, int n_in,
                              void* d_out, int out_size) {
    const float* img       = (const float*)d_in[0];
    const float* base_feat = (const float*)d_in[1];
    const float* w_bneck   = (const float*)d_in[2];
    const float* b_bneck   = (const float*)d_in[3];
    const float* bn_gamma  = (const float*)d_in[4];
    const float* bn_beta   = (const float*)d_in[5];
    const float* w_mask    = (const float*)d_in[6];
    float* out = (float*)d_out;

    k_zero<<<12, 256>>>();
    cudaMemsetAsync(out + OFF_MSP, 0, (size_t)SZ_MSP * sizeof(float), 0);
    k_bneck<<<NPIX / 256, 256>>>(base_feat, w_bneck, b_bneck);
    k_bnfin<<<1, 32>>>(bn_gamma, bn_beta);
    k_mask<<<NPIX / 128, 256>>>(w_mask, out);
    k_pal_acc<<<1024, 256>>>(img, out);
    k_pal_fin<<<12, 256>>>(out);
    k_transform<<<NPIX / 256, 256>>>(out);
}